// round 13
// baseline (speedup 1.0000x reference)
#include <cuda_runtime.h>
#include <cuda_bf16.h>

#define NV   100000
#define ND   128
#define NE   600000
#define NVD  (NV * ND)
#define NTB  1024
#define NB   ((NV + NTB - 1) / NTB)   // 98

// ---------------- scratch (device globals: no allocation allowed) ------------
__device__ float g_h0[NVD];
__device__ float g_y[NVD];
__device__ float g_h[NVD];
__device__ int   g_deg[NV];
__device__ int   g_rowptr[NV + 1];
__device__ int   g_cursor[NV];
__device__ int   g_adj[2 * NE];
__device__ float g_stats[2 * ND];
__device__ float g_mr[2 * ND];      // mean | rstd
__device__ int   g_is64;
__device__ int   g_bsum[NB];
__device__ int   g_boff[NB];
__device__ __nv_bfloat16 g_Whi[8 * ND * ND];  // [s][n][k], s = L*2+br
__device__ __nv_bfloat16 g_Wlo[8 * ND * ND];

// ---------------- edge dtype probe ------------------------------------------
__global__ void k_detect(const void* __restrict__ edges) {
    const long long* e = (const long long*)edges;
    int ok = 1;
    for (int i = 0; i < 16; i++) {
        long long v = e[i];
        if (v < 0 || v >= NV) ok = 0;
    }
    g_is64 = ok;
}

__device__ __forceinline__ void load_edge(const void* edges, int e, int& a, int& b) {
    if (g_is64) {
        longlong2 p = ((const longlong2*)edges)[e];
        a = (int)p.x; b = (int)p.y;
    } else {
        int2 p = ((const int2*)edges)[e];
        a = p.x; b = p.y;
    }
}

// ---------------- CSR build (six small kernels — known good) -----------------
__global__ void k_zero_deg() {
    int i = blockIdx.x * blockDim.x + threadIdx.x;
    if (i < NV) g_deg[i] = 0;
}

__global__ void k_count(const void* __restrict__ edges) {
    int e = blockIdx.x * blockDim.x + threadIdx.x;
    if (e < NE) {
        int a, b;
        load_edge(edges, e, a, b);
        atomicAdd(&g_deg[a], 1);
        atomicAdd(&g_deg[b], 1);
    }
}

__global__ void k_bsum() {
    __shared__ int ws[32];
    int t = threadIdx.x, lane = t & 31, wid = t >> 5;
    int idx = blockIdx.x * NTB + t;
    int v = (idx < NV) ? g_deg[idx] : 0;
    #pragma unroll
    for (int off = 16; off > 0; off >>= 1)
        v += __shfl_down_sync(0xFFFFFFFFu, v, off);
    if (lane == 0) ws[wid] = v;
    __syncthreads();
    if (wid == 0) {
        int s = ws[lane];
        #pragma unroll
        for (int off = 16; off > 0; off >>= 1)
            s += __shfl_down_sync(0xFFFFFFFFu, s, off);
        if (lane == 0) g_bsum[blockIdx.x] = s;
    }
}

__global__ void k_bscan() {
    __shared__ int ws[4];
    int t = threadIdx.x, lane = t & 31, wid = t >> 5;
    int v = (t < NB) ? g_bsum[t] : 0;
    int inc = v;
    #pragma unroll
    for (int off = 1; off < 32; off <<= 1) {
        int x = __shfl_up_sync(0xFFFFFFFFu, inc, off);
        if (lane >= off) inc += x;
    }
    if (lane == 31) ws[wid] = inc;
    __syncthreads();
    int woff = 0;
    for (int w = 0; w < wid; w++) woff += ws[w];
    if (t < NB) g_boff[t] = woff + inc - v;
    if (t == 0) g_rowptr[NV] = 2 * NE;
}

__global__ void k_apply() {
    __shared__ int ws[32];
    int t = threadIdx.x, lane = t & 31, wid = t >> 5;
    int idx = blockIdx.x * NTB + t;
    int v = (idx < NV) ? g_deg[idx] : 0;
    int inc = v;
    #pragma unroll
    for (int off = 1; off < 32; off <<= 1) {
        int x = __shfl_up_sync(0xFFFFFFFFu, inc, off);
        if (lane >= off) inc += x;
    }
    if (lane == 31) ws[wid] = inc;
    __syncthreads();
    if (wid == 0) {
        int s = ws[lane];
        #pragma unroll
        for (int off = 1; off < 32; off <<= 1) {
            int x = __shfl_up_sync(0xFFFFFFFFu, s, off);
            if (lane >= off) s += x;
        }
        ws[lane] = s;
    }
    __syncthreads();
    int excl = g_boff[blockIdx.x] + ((wid > 0) ? ws[wid - 1] : 0) + inc - v;
    if (idx < NV) { g_rowptr[idx] = excl; g_cursor[idx] = excl; }
}

__global__ void k_fill(const void* __restrict__ edges) {
    int e = blockIdx.x * blockDim.x + threadIdx.x;
    if (e < NE) {
        int a, b;
        load_edge(edges, e, a, b);
        int pa = atomicAdd(&g_cursor[a], 1);
        g_adj[pa] = b;
        int pb = atomicAdd(&g_cursor[b], 1);
        g_adj[pb] = a;
    }
}

// ---------------- weight split into bf16 hi/lo -------------------------------
__global__ void k_wsplit(const float* __restrict__ W0, const float* __restrict__ W1) {
    int i = blockIdx.x * blockDim.x + threadIdx.x;
    if (i >= 8 * ND * ND) return;
    int s = i >> 14;             // 0..7
    int L = s >> 1, br = s & 1;
    int nk = i & (ND * ND - 1);
    const float* W = br ? W1 : W0;
    float w = W[(size_t)L * ND * ND + nk];
    __nv_bfloat16 hi = __float2bfloat16_rn(w);
    __nv_bfloat16 lo = __float2bfloat16_rn(w - __bfloat162float(hi));
    g_Whi[i] = hi;
    g_Wlo[i] = lo;
}

// ---------------- fused dual tensor-core GEMM (cp.async pipelined) -----------
// x = doNorm ? relu(bn(A) (+res)) : A;  C0 = x W0^T + b0;  C1 = x W1^T + b1
#define BM 128
#define BK 32
#define LDA 40          // A split planes: 80-byte rows, conflict-free LDSM
#define LDB 136         // B resident planes: 272-byte rows, conflict-free LDSM
#define LDRAWB 144      // raw fp32 A tile row bytes (36 floats)

__device__ __forceinline__ void mma_bf16(float* c, const unsigned* a, const unsigned* b) {
    asm volatile(
        "mma.sync.aligned.m16n8k16.row.col.f32.bf16.bf16.f32 "
        "{%0,%1,%2,%3}, {%4,%5,%6,%7}, {%8,%9}, {%0,%1,%2,%3};"
        : "+f"(c[0]), "+f"(c[1]), "+f"(c[2]), "+f"(c[3])
        : "r"(a[0]), "r"(a[1]), "r"(a[2]), "r"(a[3]), "r"(b[0]), "r"(b[1]));
}

__device__ __forceinline__ void ldsm_x4(unsigned* r, unsigned addr) {
    asm volatile("ldmatrix.sync.aligned.m8n8.x4.shared.b16 {%0,%1,%2,%3}, [%4];"
                 : "=r"(r[0]), "=r"(r[1]), "=r"(r[2]), "=r"(r[3]) : "r"(addr));
}

__device__ __forceinline__ void cp16(unsigned dst, const void* src) {
    asm volatile("cp.async.cg.shared.global [%0], [%1], 16;" :: "r"(dst), "l"(src));
}
__device__ __forceinline__ void cp16p(unsigned dst, const void* src, bool ok) {
    int sz = ok ? 16 : 0;
    asm volatile("cp.async.cg.shared.global [%0], [%1], 16, %2;"
                 :: "r"(dst), "l"(src), "r"(sz));
}
__device__ __forceinline__ void cp_commit() {
    asm volatile("cp.async.commit_group;" ::: "memory");
}
__device__ __forceinline__ void cp_wait0() {
    asm volatile("cp.async.wait_group 0;" ::: "memory");
}

// smem layout in halves (bf16 units)
#define SM_AHI 0
#define SM_ALO (128 * LDA)                 // 5120
#define SM_B0H (2 * 128 * LDA)             // 10240
#define SM_B0L (SM_B0H + 128 * LDB)
#define SM_B1H (SM_B0H + 2 * 128 * LDB)
#define SM_B1L (SM_B0H + 3 * 128 * LDB)
#define SM_RAW (SM_B0H + 4 * 128 * LDB)    // raw region bytes-addressed
#define SMEM_HALVES (SM_RAW + 128 * 36 * 2)  // 89088 halves = 178176 B

__global__ __launch_bounds__(512, 1)
void k_gemm_dual(const float* __restrict__ A,
                 const __nv_bfloat16* __restrict__ Whi0,
                 const __nv_bfloat16* __restrict__ Wlo0,
                 const __nv_bfloat16* __restrict__ Whi1,
                 const __nv_bfloat16* __restrict__ Wlo1,
                 const float* __restrict__ bias0,
                 const float* __restrict__ bias1,
                 float* __restrict__ C0, float* __restrict__ C1,
                 int doNorm,
                 const float* __restrict__ gamma,
                 const float* __restrict__ beta,
                 const float* __restrict__ res) {
    extern __shared__ __nv_bfloat16 sm[];
    int tid = threadIdx.x;            // 512
    int w    = tid >> 5;              // 0..15
    int lane = tid & 31;
    int qr = lane >> 2, qc = lane & 3;
    int half = w >> 3;                // n-half
    int wm   = w & 7;                 // m rows [16wm, 16wm+16)
    int rowBase = blockIdx.x * BM;

    unsigned smb = (unsigned)__cvta_generic_to_shared(sm);
    int arow = 16 * wm + (lane & 7) + 8 * ((lane >> 3) & 1);
    int acolb = 8 * (lane >> 4);
    unsigned aoff_hi = smb + (unsigned)(SM_AHI + arow * LDA + acolb) * 2;
    unsigned aoff_lo = smb + (unsigned)(SM_ALO + arow * LDA + acolb) * 2;
    int brow = half * 64 + (lane & 7) + 8 * (lane >> 4);
    int bcolb = 8 * ((lane >> 3) & 1);
    unsigned boff0h = smb + (unsigned)(SM_B0H + brow * LDB + bcolb) * 2;
    unsigned boff0l = smb + (unsigned)(SM_B0L + brow * LDB + bcolb) * 2;
    unsigned boff1h = smb + (unsigned)(SM_B1H + brow * LDB + bcolb) * 2;
    unsigned boff1l = smb + (unsigned)(SM_B1L + brow * LDB + bcolb) * 2;

    float acc0[8][4], acc1[8][4];
    #pragma unroll
    for (int nt = 0; nt < 8; nt++)
        #pragma unroll
        for (int j = 0; j < 4; j++) { acc0[nt][j] = 0.f; acc1[nt][j] = 0.f; }

    // ---- prologue: cp.async ALL B planes (full K: 2048 x 16B chunks each) ----
    #pragma unroll
    for (int i = 0; i < 4; i++) {
        int s = i * 512 + tid;         // 2048 slots per plane
        int n = s >> 4;                // row
        int q = (s & 15) * 8;          // halves
        size_t goff = (size_t)n * ND + q;
        unsigned soff = (unsigned)(n * LDB + q);
        cp16(smb + (unsigned)(SM_B0H + soff) * 2, Whi0 + goff);
        cp16(smb + (unsigned)(SM_B0L + soff) * 2, Wlo0 + goff);
        cp16(smb + (unsigned)(SM_B1H + soff) * 2, Whi1 + goff);
        cp16(smb + (unsigned)(SM_B1L + soff) * 2, Wlo1 + goff);
    }
    // raw A tile 0
    #pragma unroll
    for (int i = 0; i < 2; i++) {
        int s = i * 512 + tid;
        int r = s >> 3;
        int q = s & 7;
        int row = rowBase + r;
        unsigned dst = smb + (unsigned)(SM_RAW * 2 + r * LDRAWB + q * 16);
        cp16p(dst, A + (size_t)row * ND + q * 4, row < NV);
    }
    cp_commit();
    cp_wait0();

    #pragma unroll
    for (int kt = 0; kt < 4; kt++) {
        int k0 = kt * BK;
        // ---- transform raw -> split bf16 planes (own bytes only) ----
        #pragma unroll
        for (int i = 0; i < 2; i++) {
            int s = i * 512 + tid;
            int r = s >> 3;
            int q = s & 7;
            int row = rowBase + r;
            int col = k0 + q * 4;
            float4 av = *(const float4*)((const char*)sm + SM_RAW * 2 + r * LDRAWB + q * 16);
            if (doNorm) {
                float4 mu = *(const float4*)(g_mr + col);
                float4 rs = *(const float4*)(g_mr + ND + col);
                float4 ga = __ldg((const float4*)(gamma + col));
                float4 be = __ldg((const float4*)(beta + col));
                av.x = (av.x - mu.x) * rs.x * ga.x + be.x;
                av.y = (av.y - mu.y) * rs.y * ga.y + be.y;
                av.z = (av.z - mu.z) * rs.z * ga.z + be.z;
                av.w = (av.w - mu.w) * rs.w * ga.w + be.w;
                if (res && row < NV) {
                    float4 rv = *(const float4*)(res + (size_t)row * ND + col);
                    av.x += rv.x; av.y += rv.y; av.z += rv.z; av.w += rv.w;
                }
                av.x = fmaxf(av.x, 0.f); av.y = fmaxf(av.y, 0.f);
                av.z = fmaxf(av.z, 0.f); av.w = fmaxf(av.w, 0.f);
                if (row >= NV) { av.x = av.y = av.z = av.w = 0.f; }
            }
            float vv[4] = {av.x, av.y, av.z, av.w};
            __nv_bfloat16 h[4], l[4];
            #pragma unroll
            for (int j = 0; j < 4; j++) {
                h[j] = __float2bfloat16_rn(vv[j]);
                l[j] = __float2bfloat16_rn(vv[j] - __bfloat162float(h[j]));
            }
            __nv_bfloat16* ah = sm + SM_AHI + r * LDA + q * 4;
            __nv_bfloat16* al = sm + SM_ALO + r * LDA + q * 4;
            *(__nv_bfloat162*)(ah)     = __nv_bfloat162{h[0], h[1]};
            *(__nv_bfloat162*)(ah + 2) = __nv_bfloat162{h[2], h[3]};
            *(__nv_bfloat162*)(al)     = __nv_bfloat162{l[0], l[1]};
            *(__nv_bfloat162*)(al + 2) = __nv_bfloat162{l[2], l[3]};
        }
        __syncthreads();

        // ---- prefetch raw A tile kt+1 (overlaps with mma below) ----
        if (kt < 3) {
            int k0n = (kt + 1) * BK;
            #pragma unroll
            for (int i = 0; i < 2; i++) {
                int s = i * 512 + tid;
                int r = s >> 3;
                int q = s & 7;
                int row = rowBase + r;
                unsigned dst = smb + (unsigned)(SM_RAW * 2 + r * LDRAWB + q * 16);
                cp16p(dst, A + (size_t)row * ND + k0n + q * 4, row < NV);
            }
            cp_commit();
        }

        // ---- mma over tile kt ----
        #pragma unroll
        for (int kc = 0; kc < BK; kc += 16) {
            unsigned ka = (unsigned)(kc * 2);
            unsigned kb = (unsigned)((k0 + kc) * 2);
            unsigned ah[4], al[4];
            ldsm_x4(ah, aoff_hi + ka);
            ldsm_x4(al, aoff_lo + ka);
            #pragma unroll
            for (int j = 0; j < 4; j++) {          // nt pair (2j, 2j+1)
                unsigned poff = (unsigned)(j * 16 * LDB * 2) + kb;
                unsigned b0h[4], b0l[4], b1h[4], b1l[4];
                ldsm_x4(b0h, boff0h + poff);
                ldsm_x4(b0l, boff0l + poff);
                ldsm_x4(b1h, boff1h + poff);
                ldsm_x4(b1l, boff1l + poff);
                mma_bf16(acc0[2 * j],     ah, b0h);
                mma_bf16(acc0[2 * j],     ah, b0l + 0);
                mma_bf16(acc0[2 * j],     al, b0h);
                mma_bf16(acc0[2 * j + 1], ah, b0h + 2);
                mma_bf16(acc0[2 * j + 1], ah, b0l + 2);
                mma_bf16(acc0[2 * j + 1], al, b0h + 2);
                mma_bf16(acc1[2 * j],     ah, b1h);
                mma_bf16(acc1[2 * j],     ah, b1l + 0);
                mma_bf16(acc1[2 * j],     al, b1h);
                mma_bf16(acc1[2 * j + 1], ah, b1h + 2);
                mma_bf16(acc1[2 * j + 1], ah, b1l + 2);
                mma_bf16(acc1[2 * j + 1], al, b1h + 2);
            }
        }
        if (kt < 3) {
            __syncthreads();   // all warps done reading split A of tile kt
            cp_wait0();        // own raw bytes for tile kt+1 arrived
        }
    }

    int gr0 = rowBase + 16 * wm + qr;
    int gr1 = gr0 + 8;
    #pragma unroll
    for (int nt = 0; nt < 8; nt++) {
        int col = half * 64 + nt * 8 + 2 * qc;
        float p0 = __ldg(bias0 + col), p1 = __ldg(bias0 + col + 1);
        float q0 = __ldg(bias1 + col), q1 = __ldg(bias1 + col + 1);
        if (gr0 < NV) {
            *(float2*)(C0 + (size_t)gr0 * ND + col) =
                make_float2(acc0[nt][0] + p0, acc0[nt][1] + p1);
            *(float2*)(C1 + (size_t)gr0 * ND + col) =
                make_float2(acc1[nt][0] + q0, acc1[nt][1] + q1);
        }
        if (gr1 < NV) {
            *(float2*)(C0 + (size_t)gr1 * ND + col) =
                make_float2(acc0[nt][2] + p0, acc0[nt][3] + p1);
            *(float2*)(C1 + (size_t)gr1 * ND + col) =
                make_float2(acc1[nt][2] + q0, acc1[nt][3] + q1);
        }
    }
}

// ---------------- misc -------------------------------------------------------
__global__ void k_zero_stats() {
    int i = threadIdx.x;
    if (i < 2 * ND) g_stats[i] = 0.f;
}

__global__ void k_finalize() {
    int c = threadIdx.x;   // 128
    float mean = g_stats[c] * (1.0f / NV);
    float var  = g_stats[ND + c] * (1.0f / NV) - mean * mean;
    g_mr[c]      = mean;
    g_mr[ND + c] = rsqrtf(var + 1e-5f);
}

// ---------------- aggregate: out[v] = h0[v] + sum_{u in N(v)} y[u] -----------
// column-split 4-pass (y working set 12.8 MB, L2-resident; evict-first hints on
// streamed h0/out). Gathers issued in mask-predicated batches of 8 so every
// node, including its tail, runs at MLP=8 (clamped index is always in-range).
__global__ void k_agg(const float* __restrict__ h0, const float* __restrict__ y,
                      float* __restrict__ out, int doStats) {
    int lane   = threadIdx.x & 31;
    int warp   = (blockIdx.x * blockDim.x + threadIdx.x) >> 5;
    int nwarps = (gridDim.x * blockDim.x) >> 5;

    #pragma unroll
    for (int p = 0; p < 4; p++) {
        int c = p * 32 + lane;          // this lane's column
        float csum = 0.f, csq = 0.f;

        for (int v = warp; v < NV; v += nwarps) {
            float acc = __ldcs(h0 + (size_t)v * ND + c);
            int beg = g_rowptr[v], end = g_rowptr[v + 1];
            for (int j = beg; j < end; j += 8) {
                int rem = end - j;       // >= 1
                float a[8], m[8];
                #pragma unroll
                for (int t = 0; t < 8; t++) {
                    int idx = j + ((t < rem) ? t : (rem - 1));
                    a[t] = y[(size_t)g_adj[idx] * ND + c];
                    m[t] = (t < rem) ? 1.f : 0.f;
                }
                float s0 = fmaf(m[0], a[0], m[1] * a[1]);
                float s1 = fmaf(m[2], a[2], m[3] * a[3]);
                float s2 = fmaf(m[4], a[4], m[5] * a[5]);
                float s3 = fmaf(m[6], a[6], m[7] * a[7]);
                acc += (s0 + s1) + (s2 + s3);
            }
            __stcs(out + (size_t)v * ND + c, acc);
            csum += acc;
            csq  += acc * acc;
        }
        if (doStats) {
            atomicAdd(&g_stats[c], csum);
            atomicAdd(&g_stats[ND + c], csq);
        }
    }
}

// ---------------- launch -----------------------------------------------------
extern "C" void kernel_launch(void* const* d_in, const int* in_sizes, int n_in,
                              void* d_out, int out_size) {
    const float* feat  = (const float*)d_in[0];
    const void*  edges = d_in[1];
    const float* W0    = (const float*)d_in[2];
    const float* b0    = (const float*)d_in[3];
    const float* W1    = (const float*)d_in[4];
    const float* b1    = (const float*)d_in[5];
    const float* gamma = (const float*)d_in[6];
    const float* beta  = (const float*)d_in[7];
    float*       out   = (float*)d_out;

    float* ph0; cudaGetSymbolAddress((void**)&ph0, g_h0);
    float* py;  cudaGetSymbolAddress((void**)&py,  g_y);
    float* ph;  cudaGetSymbolAddress((void**)&ph,  g_h);
    __nv_bfloat16* pwh; cudaGetSymbolAddress((void**)&pwh, g_Whi);
    __nv_bfloat16* pwl; cudaGetSymbolAddress((void**)&pwl, g_Wlo);

    const int smemBytes = SMEM_HALVES * (int)sizeof(__nv_bfloat16);  // 178176
    cudaFuncSetAttribute(k_gemm_dual, cudaFuncAttributeMaxDynamicSharedMemorySize,
                         smemBytes);

    const int gemmBlocks = (NV + BM - 1) / BM;   // 782
    const int aggBlocks  = 2368;                 // 16 * 148

    // 1: detect, 2: wsplit, 3: zero_deg, 4: layer-0 GEMM (profiled slot)
    k_detect<<<1, 1>>>(edges);
    k_wsplit<<<(8 * ND * ND + 255) / 256, 256>>>(W0, W1);
    k_zero_deg<<<(NV + 255) / 256, 256>>>();
    k_gemm_dual<<<gemmBlocks, 512, smemBytes>>>(
        feat, pwh, pwl, pwh + (size_t)ND * ND, pwl + (size_t)ND * ND,
        b0, b1, ph0, py, 0, nullptr, nullptr, nullptr);

    // CSR build
    k_count<<<(NE + 255) / 256, 256>>>(edges);
    k_bsum<<<NB, NTB>>>();
    k_bscan<<<1, 128>>>();
    k_apply<<<NB, NTB>>>();
    k_fill<<<(NE + 255) / 256, 256>>>(edges);

    // layer 0 aggregate + stats
    k_zero_stats<<<1, 256>>>();
    k_agg<<<aggBlocks, 256>>>(ph0, py, ph, 1);
    k_finalize<<<1, ND>>>();

    // layers 1..3: GEMM (with fused BN of previous layer) -> aggregate
    for (int L = 1; L < 4; L++) {
        const __nv_bfloat16* wh0 = pwh + (size_t)(L * 2 + 0) * ND * ND;
        const __nv_bfloat16* wl0 = pwl + (size_t)(L * 2 + 0) * ND * ND;
        const __nv_bfloat16* wh1 = pwh + (size_t)(L * 2 + 1) * ND * ND;
        const __nv_bfloat16* wl1 = pwl + (size_t)(L * 2 + 1) * ND * ND;
        const float* res = (L == 3) ? feat : nullptr;   // x3 = relu(bn(h2)+feat)
        k_gemm_dual<<<gemmBlocks, 512, smemBytes>>>(
            ph, wh0, wl0, wh1, wl1, b0 + L * ND, b1 + L * ND, ph0, py,
            1, gamma + (L - 1) * ND, beta + (L - 1) * ND, res);
        if (L < 3) {
            k_zero_stats<<<1, 256>>>();
            k_agg<<<aggBlocks, 256>>>(ph0, py, ph, 1);
            k_finalize<<<1, ND>>>();
        } else {
            k_agg<<<aggBlocks, 256>>>(ph0, py, out, 0);
        }
    }
}